// round 15
// baseline (speedup 1.0000x reference)
#include <cuda_runtime.h>
#include <cuda_fp16.h>
#include <stdint.h>

// Problem shape (fixed by dataset): N=50000, E=800000, Fin=Fhid=128, Fout=64
#define NMAX 50176
#define EMAX 800000

// -------- static device scratch (no allocations; referenced directly) ------
__device__ int    g_hi_nonzero;               // dtype probe (monotone 0->1)
__device__ float  g_dinv[NMAX];
__device__ int    g_cnt[NMAX];
__device__ int    g_rowptr[NMAX + 1];
__device__ int    g_cursor[NMAX];
__device__ volatile int g_sflag[64];          // lookback: 0=none,1=agg,2=prefix
__device__ volatile int g_sagg[64];
__device__ volatile int g_spref[64];
__device__ int2   g_emeta[EMAX];              // {src, ew-as-int-bits}
__device__ __half g_xwh[(size_t)NMAX * 128];  // fp16(x @ W0)   gather source
__device__ __half g_hh[(size_t)NMAX * 128];   // fp16 layer-1 activations
__device__ __half g_hwh[(size_t)NMAX * 64];   // fp16(h @ W1)   gather source

// ----------------------------------------------------------------
// Probe edge_index dtype + zero g_cnt + reset scan flags, one pass.
// (Same-stream ordering guarantees flags are cleared before k_scan_fused.)
__global__ void k_detect_init(const int* __restrict__ ei32, int E, int N) {
    int i = blockIdx.x * blockDim.x + threadIdx.x;
    int samples = E < 65536 ? E : 65536;
    if (i < samples) {
        if (ei32[2 * i + 1] != 0) atomicOr(&g_hi_nonzero, 1);
    }
    if (i < N) g_cnt[i] = 0;
    if (i < 64) g_sflag[i] = 0;
}

__device__ __forceinline__ int clampN(int v, int N) {
    v = v < 0 ? 0 : v;
    return v >= N ? N - 1 : v;
}

// per-edge in-degree histogram; 4 edges/thread via int4 index loads
__global__ void k_count(const int* __restrict__ ei32, int E, int N) {
    int base = (blockIdx.x * blockDim.x + threadIdx.x) * 4;
    if (base >= E) return;
    int n = E - base; if (n > 4) n = 4;
    int c[4];
    if (g_hi_nonzero == 0) {                    // int64: col low words
        const int4* p = (const int4*)&ei32[2 * E + 2 * base];
        int4 w0 = p[0], w1 = p[1];
        c[0] = w0.x; c[1] = w0.z; c[2] = w1.x; c[3] = w1.z;
    } else {                                    // int32
        int4 w = *(const int4*)&ei32[E + base];
        c[0] = w.x; c[1] = w.y; c[2] = w.z; c[3] = w.w;
    }
#pragma unroll
    for (int j = 0; j < 4; j++) {
        if (j < n) atomicAdd(&g_cnt[clampN(c[j], N)], 1);
    }
}

// ---- single-kernel exclusive scan (decoupled lookback, 49 blocks) ----
__global__ void k_scan_fused(int N, int E) {
    __shared__ int wsum[32];
    __shared__ int blockpfx;
    const int t = threadIdx.x, lane = t & 31, wid = t >> 5;
    const int b = blockIdx.x;
    const int i = b * 1024 + t;
    int v = (i < N) ? g_cnt[i] : 0;
    // warp inclusive scan
    int x = v;
#pragma unroll
    for (int o = 1; o < 32; o <<= 1) {
        int y = __shfl_up_sync(0xffffffffu, x, o);
        if (lane >= o) x += y;
    }
    if (lane == 31) wsum[wid] = x;
    __syncthreads();
    if (wid == 0) {
        int s = wsum[lane];
#pragma unroll
        for (int o = 1; o < 32; o <<= 1) {
            int y = __shfl_up_sync(0xffffffffu, s, o);
            if (lane >= o) s += y;
        }
        wsum[lane] = s;
    }
    __syncthreads();
    int excl_local = (wid ? wsum[wid - 1] : 0) + x - v;
    int total = wsum[31];
    if (t == 0) {
        int pfx = 0;
        if (b == 0) {
            g_spref[0] = total; __threadfence(); g_sflag[0] = 2;
        } else {
            g_sagg[b] = total; __threadfence(); g_sflag[b] = 1;
            for (int j = b - 1; j >= 0;) {
                int f;
                while ((f = g_sflag[j]) == 0) {}
                __threadfence();
                if (f == 2) { pfx += g_spref[j]; break; }
                pfx += g_sagg[j]; j--;
            }
            g_spref[b] = pfx + total; __threadfence(); g_sflag[b] = 2;
        }
        blockpfx = pfx;
    }
    __syncthreads();
    int r = excl_local + blockpfx;
    if (i < N) { g_rowptr[i] = r; g_cursor[i] = r; }
    if (i == 0) g_rowptr[N] = E;
}

// per-edge: place {src, ew} into CSR slot of target; 4 edges/thread, int4 loads
__global__ void k_place(const int* __restrict__ ei32,
                        const float* __restrict__ ew, int E, int N) {
    int base = (blockIdx.x * blockDim.x + threadIdx.x) * 4;
    if (base >= E) return;
    int n = E - base; if (n > 4) n = 4;
    int r[4], c[4];
    if (g_hi_nonzero == 0) {                    // int64 low words
        const int4* pr = (const int4*)&ei32[2 * base];
        int4 a0 = pr[0], a1 = pr[1];
        r[0] = a0.x; r[1] = a0.z; r[2] = a1.x; r[3] = a1.z;
        const int4* pc = (const int4*)&ei32[2 * E + 2 * base];
        int4 b0 = pc[0], b1 = pc[1];
        c[0] = b0.x; c[1] = b0.z; c[2] = b1.x; c[3] = b1.z;
    } else {
        int4 a = *(const int4*)&ei32[base];
        r[0] = a.x; r[1] = a.y; r[2] = a.z; r[3] = a.w;
        int4 b = *(const int4*)&ei32[E + base];
        c[0] = b.x; c[1] = b.y; c[2] = b.z; c[3] = b.w;
    }
    float4 wv = *(const float4*)&ew[base];
    float w[4] = {wv.x, wv.y, wv.z, wv.w};
#pragma unroll
    for (int j = 0; j < 4; j++) {
        if (j < n) {
            int pos = atomicAdd(&g_cursor[clampN(c[j], N)], 1);
            if (pos >= 0 && pos < EMAX)
                g_emeta[pos] = make_int2(clampN(r[j], N), __float_as_int(w[j]));
        }
    }
}

// per-node: weighted degree (self-loop 1 + segment ew sum) -> dinv
__global__ void k_deg(int N) {
    int i = blockIdx.x * blockDim.x + threadIdx.x;
    if (i >= N) return;
    int s = g_rowptr[i], e = g_rowptr[i + 1];
    float d = 1.0f;
    for (int p = s; p < e; p++) d += __int_as_float(g_emeta[p].y);
    g_dinv[i] = rsqrtf(d);
}

// ----------------------------------------------------------------
// HMMA GEMM: C_fp16[M,BN_] = A[M,K] @ B_fp32[K,BN_], fp32 accumulate.
// A is fp32 (layer 0: x) or fp16 (layer 1: g_hh).
template <int BN_, bool AHALF>
__global__ __launch_bounds__(256)
void k_hgemm(const float* __restrict__ Ain, const float* __restrict__ B,
             __half* __restrict__ C, int M, int K) {
    constexpr int BM = 128, BKC = 64;
    constexpr int SA = BKC + 8;
    constexpr int SB = BN_ + 8;
    constexpr int WN = BN_ / 4;
    constexpr int NF = WN / 8;

    __shared__ __half As[BM * SA];
    __shared__ __half Bs[BKC * SB];

    const int tid  = threadIdx.x;
    const int wid  = tid >> 5;
    const int lane = tid & 31;
    const int bm   = blockIdx.x * BM;
    const int warp_m = (wid >> 2) * 64;
    const int warp_n = (wid & 3) * WN;

    float acc[4][NF][4];
#pragma unroll
    for (int i = 0; i < 4; i++)
#pragma unroll
        for (int j = 0; j < NF; j++)
#pragma unroll
            for (int r = 0; r < 4; r++) acc[i][j][r] = 0.0f;

    for (int c0 = 0; c0 < K; c0 += BKC) {
        // stage A chunk: BM x BKC -> fp16 smem
        {
            constexpr int NIT = BM * BKC / 8 / 256;   // 8 elems/thread/iter
#pragma unroll
            for (int p = 0; p < NIT; p++) {
                int idx = p * 256 + tid;
                int row = idx / (BKC / 8);
                int k8  = (idx % (BKC / 8)) * 8;
                int gm  = bm + row;
                __half2 h[4];
                if constexpr (AHALF) {
                    uint4 raw = make_uint4(0, 0, 0, 0);
                    if (gm < M)
                        raw = *(const uint4*)&g_hh[(size_t)gm * K + c0 + k8];
                    h[0] = *(__half2*)&raw.x; h[1] = *(__half2*)&raw.y;
                    h[2] = *(__half2*)&raw.z; h[3] = *(__half2*)&raw.w;
                } else {
                    float4 v0 = make_float4(0.f, 0.f, 0.f, 0.f), v1 = v0;
                    if (gm < M) {
                        const float* p0 = Ain + (size_t)gm * K + c0 + k8;
                        v0 = *(const float4*)(p0);
                        v1 = *(const float4*)(p0 + 4);
                    }
                    h[0] = __floats2half2_rn(v0.x, v0.y);
                    h[1] = __floats2half2_rn(v0.z, v0.w);
                    h[2] = __floats2half2_rn(v1.x, v1.y);
                    h[3] = __floats2half2_rn(v1.z, v1.w);
                }
                __half2* dst = (__half2*)&As[row * SA + k8];
                dst[0] = h[0]; dst[1] = h[1]; dst[2] = h[2]; dst[3] = h[3];
            }
        }
        // stage B chunk: BKC x BN_ fp32 -> fp16 smem
        {
            constexpr int NF4 = BKC * BN_ / 4;
#pragma unroll
            for (int p = 0; p < NF4 / 256; p++) {
                int idx = p * 256 + tid;
                int row = idx / (BN_ / 4);
                int c4  = idx % (BN_ / 4);
                float4 v = *(const float4*)&B[(size_t)(c0 + row) * BN_ + c4 * 4];
                __half2* dst = (__half2*)&Bs[row * SB + c4 * 4];
                dst[0] = __floats2half2_rn(v.x, v.y);
                dst[1] = __floats2half2_rn(v.z, v.w);
            }
        }
        __syncthreads();

#pragma unroll
        for (int ks = 0; ks < BKC / 16; ks++) {
            const int kb = ks * 16;
            uint32_t a[4][4];
#pragma unroll
            for (int mf = 0; mf < 4; mf++) {
                uint32_t addr = (uint32_t)__cvta_generic_to_shared(
                    &As[(warp_m + mf * 16 + (lane & 15)) * SA + kb + (lane >> 4) * 8]);
                asm volatile(
                    "ldmatrix.sync.aligned.m8n8.x4.shared.b16 {%0,%1,%2,%3}, [%4];"
                    : "=r"(a[mf][0]), "=r"(a[mf][1]), "=r"(a[mf][2]), "=r"(a[mf][3])
                    : "r"(addr));
            }
            uint32_t b[NF][2];
#pragma unroll
            for (int nq = 0; nq < NF / 2; nq++) {
                uint32_t addr = (uint32_t)__cvta_generic_to_shared(
                    &Bs[(kb + (lane & 15)) * SB + warp_n + nq * 16 + (lane >> 4) * 8]);
                asm volatile(
                    "ldmatrix.sync.aligned.m8n8.x4.trans.shared.b16 {%0,%1,%2,%3}, [%4];"
                    : "=r"(b[2 * nq][0]), "=r"(b[2 * nq][1]),
                      "=r"(b[2 * nq + 1][0]), "=r"(b[2 * nq + 1][1])
                    : "r"(addr));
            }
#pragma unroll
            for (int mf = 0; mf < 4; mf++)
#pragma unroll
                for (int nf = 0; nf < NF; nf++) {
                    asm volatile(
                        "mma.sync.aligned.m16n8k16.row.col.f32.f16.f16.f32 "
                        "{%0,%1,%2,%3}, {%4,%5,%6,%7}, {%8,%9}, {%0,%1,%2,%3};"
                        : "+f"(acc[mf][nf][0]), "+f"(acc[mf][nf][1]),
                          "+f"(acc[mf][nf][2]), "+f"(acc[mf][nf][3])
                        : "r"(a[mf][0]), "r"(a[mf][1]), "r"(a[mf][2]), "r"(a[mf][3]),
                          "r"(b[nf][0]), "r"(b[nf][1]));
                }
        }
        __syncthreads();
    }

#pragma unroll
    for (int mf = 0; mf < 4; mf++) {
#pragma unroll
        for (int nf = 0; nf < NF; nf++) {
            int col  = warp_n + nf * 8 + 2 * (lane & 3);
            int row0 = bm + warp_m + mf * 16 + (lane >> 2);
            int row1 = row0 + 8;
            if (row0 < M) {
                __half2 h = __floats2half2_rn(acc[mf][nf][0], acc[mf][nf][1]);
                *(__half2*)&C[(size_t)row0 * BN_ + col] = h;
            }
            if (row1 < M) {
                __half2 h = __floats2half2_rn(acc[mf][nf][2], acc[mf][nf][3]);
                *(__half2*)&C[(size_t)row1 * BN_ + col] = h;
            }
        }
    }
}

// ----------------------------------------------------------------
// One warp per destination node: self-loop + CSR gather (fp16 src, fp32 acc)
// + bias + ReLU.  F=128 -> dst fp16 (g_hh); F=64 -> dst fp32 (final out).
template <int F>
__global__ __launch_bounds__(256)
void k_agg(const __half* __restrict__ src, const float* __restrict__ bias,
           float* __restrict__ outbuf, int N) {
    const int gw   = (blockIdx.x * blockDim.x + threadIdx.x) >> 5;
    const int lane = threadIdx.x & 31;
    if (gw >= N) return;

    const int start = g_rowptr[gw];
    const int end   = g_rowptr[gw + 1];
    const float dc  = g_dinv[gw];

    if constexpr (F == 128) {
        float4 acc;
        {
            uint2 raw = ((const uint2*)(src + (size_t)gw * F))[lane];
            float2 a = __half22float2(*(__half2*)&raw.x);
            float2 b = __half22float2(*(__half2*)&raw.y);
            acc = make_float4(dc * a.x, dc * a.y, dc * b.x, dc * b.y);
        }
        int e = start;
        for (; e + 4 <= end; e += 4) {
            int2 m0 = g_emeta[e],     m1 = g_emeta[e + 1];
            int2 m2 = g_emeta[e + 2], m3 = g_emeta[e + 3];
            float w0 = __int_as_float(m0.y) * g_dinv[m0.x];
            float w1 = __int_as_float(m1.y) * g_dinv[m1.x];
            float w2 = __int_as_float(m2.y) * g_dinv[m2.x];
            float w3 = __int_as_float(m3.y) * g_dinv[m3.x];
            uint2 r0 = ((const uint2*)(src + (size_t)m0.x * F))[lane];
            uint2 r1 = ((const uint2*)(src + (size_t)m1.x * F))[lane];
            uint2 r2 = ((const uint2*)(src + (size_t)m2.x * F))[lane];
            uint2 r3 = ((const uint2*)(src + (size_t)m3.x * F))[lane];
            float2 a0 = __half22float2(*(__half2*)&r0.x), b0 = __half22float2(*(__half2*)&r0.y);
            float2 a1 = __half22float2(*(__half2*)&r1.x), b1 = __half22float2(*(__half2*)&r1.y);
            float2 a2 = __half22float2(*(__half2*)&r2.x), b2 = __half22float2(*(__half2*)&r2.y);
            float2 a3 = __half22float2(*(__half2*)&r3.x), b3 = __half22float2(*(__half2*)&r3.y);
            acc.x += w0 * a0.x + w1 * a1.x + w2 * a2.x + w3 * a3.x;
            acc.y += w0 * a0.y + w1 * a1.y + w2 * a2.y + w3 * a3.y;
            acc.z += w0 * b0.x + w1 * b1.x + w2 * b2.x + w3 * b3.x;
            acc.w += w0 * b0.y + w1 * b1.y + w2 * b2.y + w3 * b3.y;
        }
        for (; e < end; e++) {
            int2 m = g_emeta[e];
            float w = __int_as_float(m.y) * g_dinv[m.x];
            uint2 r = ((const uint2*)(src + (size_t)m.x * F))[lane];
            float2 a = __half22float2(*(__half2*)&r.x);
            float2 b = __half22float2(*(__half2*)&r.y);
            acc.x += w * a.x; acc.y += w * a.y;
            acc.z += w * b.x; acc.w += w * b.y;
        }
        float4 bv = ((const float4*)bias)[lane];
        acc.x = fmaxf(dc * acc.x + bv.x, 0.f);
        acc.y = fmaxf(dc * acc.y + bv.y, 0.f);
        acc.z = fmaxf(dc * acc.z + bv.z, 0.f);
        acc.w = fmaxf(dc * acc.w + bv.w, 0.f);
        uint2 hout;
        *(__half2*)&hout.x = __floats2half2_rn(acc.x, acc.y);
        *(__half2*)&hout.y = __floats2half2_rn(acc.z, acc.w);
        ((uint2*)(g_hh + (size_t)gw * F))[lane] = hout;
    } else {
        float2 acc;
        {
            unsigned raw = ((const unsigned*)(src + (size_t)gw * F))[lane];
            float2 a = __half22float2(*(__half2*)&raw);
            acc = make_float2(dc * a.x, dc * a.y);
        }
        int e = start;
        for (; e + 4 <= end; e += 4) {
            int2 m0 = g_emeta[e],     m1 = g_emeta[e + 1];
            int2 m2 = g_emeta[e + 2], m3 = g_emeta[e + 3];
            float w0 = __int_as_float(m0.y) * g_dinv[m0.x];
            float w1 = __int_as_float(m1.y) * g_dinv[m1.x];
            float w2 = __int_as_float(m2.y) * g_dinv[m2.x];
            float w3 = __int_as_float(m3.y) * g_dinv[m3.x];
            unsigned r0 = ((const unsigned*)(src + (size_t)m0.x * F))[lane];
            unsigned r1 = ((const unsigned*)(src + (size_t)m1.x * F))[lane];
            unsigned r2 = ((const unsigned*)(src + (size_t)m2.x * F))[lane];
            unsigned r3 = ((const unsigned*)(src + (size_t)m3.x * F))[lane];
            float2 a0 = __half22float2(*(__half2*)&r0);
            float2 a1 = __half22float2(*(__half2*)&r1);
            float2 a2 = __half22float2(*(__half2*)&r2);
            float2 a3 = __half22float2(*(__half2*)&r3);
            acc.x += w0 * a0.x + w1 * a1.x + w2 * a2.x + w3 * a3.x;
            acc.y += w0 * a0.y + w1 * a1.y + w2 * a2.y + w3 * a3.y;
        }
        for (; e < end; e++) {
            int2 m = g_emeta[e];
            float w = __int_as_float(m.y) * g_dinv[m.x];
            unsigned r = ((const unsigned*)(src + (size_t)m.x * F))[lane];
            float2 a = __half22float2(*(__half2*)&r);
            acc.x += w * a.x; acc.y += w * a.y;
        }
        float2 bv = ((const float2*)bias)[lane];
        acc.x = fmaxf(dc * acc.x + bv.x, 0.f);
        acc.y = fmaxf(dc * acc.y + bv.y, 0.f);
        ((float2*)(outbuf + (size_t)gw * F))[lane] = acc;
    }
}

// ----------------------------------------------------------------
extern "C" void kernel_launch(void* const* d_in, const int* in_sizes, int n_in,
                              void* d_out, int out_size) {
    const float* x    = (const float*)d_in[0];
    const int*   ei32 = (const int*)d_in[1];     // raw words; dtype probed on device
    const float* ew   = (const float*)d_in[2];
    const float* W0   = (const float*)d_in[3];
    const float* b0   = (const float*)d_in[4];
    const float* W1   = (const float*)d_in[5];
    const float* b1   = (const float*)d_in[6];
    float* out = (float*)d_out;

    const int Fh  = in_sizes[4];            // 128
    const int Fo  = in_sizes[6];            // 64
    const int Fin = in_sizes[3] / Fh;       // 128
    const int N   = in_sizes[0] / Fin;      // 50000
    const int E   = in_sizes[2];            // 800000

    // side stream + events, created once on the first (uncaptured) call
    static cudaStream_t s2 = nullptr;
    static cudaEvent_t evFork = nullptr, evJoin = nullptr;
    if (s2 == nullptr) {
        cudaStreamCreateWithFlags(&s2, cudaStreamNonBlocking);
        cudaEventCreateWithFlags(&evFork, cudaEventDisableTiming);
        cudaEventCreateWithFlags(&evJoin, cudaEventDisableTiming);
    }

    __half* xwh = nullptr; cudaGetSymbolAddress((void**)&xwh, g_xwh);
    __half* hwh = nullptr; cudaGetSymbolAddress((void**)&hwh, g_hwh);

    const int TB = 256;
    const int nScanBlocks = (N + 1023) / 1024;
    const int diGrid = ((N > 65536 ? N : 65536) + TB - 1) / TB;

    // fork: GEMM-1 (depends only on inputs) runs on s2, overlapping CSR prep
    cudaEventRecord(evFork, 0);
    cudaStreamWaitEvent(s2, evFork, 0);
    k_hgemm<128, false><<<(N + 127) / 128, 256, 0, s2>>>(x, W0, xwh, N, Fin);
    cudaEventRecord(evJoin, s2);

    // CSR prep chain on the main stream
    k_detect_init<<<diGrid, TB>>>(ei32, E, N);
    k_count<<<(E / 4 + TB - 1) / TB, TB>>>(ei32, E, N);
    k_scan_fused<<<nScanBlocks, 1024>>>(N, E);
    k_place<<<(E / 4 + TB - 1) / TB, TB>>>(ei32, ew, E, N);
    k_deg<<<(N + TB - 1) / TB, TB>>>(N);

    // join: agg-1 needs both CSR prep and GEMM-1
    cudaStreamWaitEvent(0, evJoin, 0);
    k_agg<128><<<(N * 32 + TB - 1) / TB, TB>>>(xwh, b0, nullptr, N);

    // layer 2
    k_hgemm<64, true><<<(N + 127) / 128, 256>>>(nullptr, W1, hwh, N, Fh);
    k_agg<64><<<(N * 32 + TB - 1) / TB, TB>>>(hwh, b1, out, N);
}

// round 16
// speedup vs baseline: 1.0596x; 1.0596x over previous
#include <cuda_runtime.h>
#include <cuda_fp16.h>
#include <stdint.h>

// Problem shape (fixed by dataset): N=50000, E=800000, Fin=Fhid=128, Fout=64
#define NMAX 50176
#define EMAX 800000

// -------- static device scratch (no allocations; referenced directly) ------
__device__ int    g_hi_nonzero;               // dtype probe (monotone 0->1)
__device__ float  g_dinv[NMAX];
__device__ int    g_cnt[NMAX];
__device__ int    g_rowptr[NMAX + 1];
__device__ int    g_cursor[NMAX];
__device__ int2   g_emeta[EMAX];              // {src, ew-as-int-bits}
__device__ __half g_xwh[(size_t)NMAX * 128];  // fp16(x @ W0)   gather source
__device__ __half g_hh[(size_t)NMAX * 128];   // fp16 layer-1 activations
__device__ __half g_hwh[(size_t)NMAX * 64];   // fp16(h @ W1)   gather source

// ----------------------------------------------------------------
// Probe edge_index dtype + zero g_cnt, one pass.
__global__ void k_detect_init(const int* __restrict__ ei32, int E, int N) {
    int i = blockIdx.x * blockDim.x + threadIdx.x;
    int samples = E < 65536 ? E : 65536;
    if (i < samples) {
        if (ei32[2 * i + 1] != 0) atomicOr(&g_hi_nonzero, 1);
    }
    if (i < N) g_cnt[i] = 0;
}

__device__ __forceinline__ int clampN(int v, int N) {
    v = v < 0 ? 0 : v;
    return v >= N ? N - 1 : v;
}

// per-edge in-degree histogram; 4 edges/thread via int4 index loads
__global__ void k_count(const int* __restrict__ ei32, int E, int N) {
    int base = (blockIdx.x * blockDim.x + threadIdx.x) * 4;
    if (base >= E) return;
    int n = E - base; if (n > 4) n = 4;
    int c[4];
    if (g_hi_nonzero == 0) {                    // int64: col low words
        const int4* p = (const int4*)&ei32[2 * E + 2 * base];
        int4 w0 = p[0], w1 = p[1];
        c[0] = w0.x; c[1] = w0.z; c[2] = w1.x; c[3] = w1.z;
    } else {                                    // int32
        int4 w = *(const int4*)&ei32[E + base];
        c[0] = w.x; c[1] = w.y; c[2] = w.z; c[3] = w.w;
    }
#pragma unroll
    for (int j = 0; j < 4; j++) {
        if (j < n) atomicAdd(&g_cnt[clampN(c[j], N)], 1);
    }
}

// ---- one-pass polling-free exclusive scan ----
// Each block redundantly sums cnt[0 .. b*1024) for its global prefix
// (coalesced L2 reads), then shuffle-scans its own 1024 elements.
__global__ void k_scan_onepass(int N, int E) {
    __shared__ int red[32];
    __shared__ int wsum[32];
    __shared__ int bpfx;
    const int t = threadIdx.x, lane = t & 31, wid = t >> 5;
    const int b = blockIdx.x;
    const int i = b * 1024 + t;

    // 1) global prefix of this block: sum of all preceding elements
    int pre = 0;
    for (int j = t; j < b * 1024; j += 1024) pre += g_cnt[j];
#pragma unroll
    for (int o = 16; o > 0; o >>= 1)
        pre += __shfl_down_sync(0xffffffffu, pre, o);
    if (lane == 0) red[wid] = pre;
    __syncthreads();
    if (wid == 0) {
        int s = red[lane];
#pragma unroll
        for (int o = 16; o > 0; o >>= 1)
            s += __shfl_down_sync(0xffffffffu, s, o);
        if (lane == 0) bpfx = s;
    }

    // 2) local inclusive scan of own 1024 elements
    int v = (i < N) ? g_cnt[i] : 0;
    int x = v;
#pragma unroll
    for (int o = 1; o < 32; o <<= 1) {
        int y = __shfl_up_sync(0xffffffffu, x, o);
        if (lane >= o) x += y;
    }
    if (lane == 31) wsum[wid] = x;
    __syncthreads();
    if (wid == 0) {
        int s = wsum[lane];
#pragma unroll
        for (int o = 1; o < 32; o <<= 1) {
            int y = __shfl_up_sync(0xffffffffu, s, o);
            if (lane >= o) s += y;
        }
        wsum[lane] = s;
    }
    __syncthreads();
    int r = bpfx + (wid ? wsum[wid - 1] : 0) + x - v;   // global exclusive
    if (i < N) { g_rowptr[i] = r; g_cursor[i] = r; }
    if (i == 0) g_rowptr[N] = E;
}

// per-edge: place {src, ew} into CSR slot of target; 4 edges/thread, int4 loads
__global__ void k_place(const int* __restrict__ ei32,
                        const float* __restrict__ ew, int E, int N) {
    int base = (blockIdx.x * blockDim.x + threadIdx.x) * 4;
    if (base >= E) return;
    int n = E - base; if (n > 4) n = 4;
    int r[4], c[4];
    if (g_hi_nonzero == 0) {                    // int64 low words
        const int4* pr = (const int4*)&ei32[2 * base];
        int4 a0 = pr[0], a1 = pr[1];
        r[0] = a0.x; r[1] = a0.z; r[2] = a1.x; r[3] = a1.z;
        const int4* pc = (const int4*)&ei32[2 * E + 2 * base];
        int4 b0 = pc[0], b1 = pc[1];
        c[0] = b0.x; c[1] = b0.z; c[2] = b1.x; c[3] = b1.z;
    } else {
        int4 a = *(const int4*)&ei32[base];
        r[0] = a.x; r[1] = a.y; r[2] = a.z; r[3] = a.w;
        int4 b = *(const int4*)&ei32[E + base];
        c[0] = b.x; c[1] = b.y; c[2] = b.z; c[3] = b.w;
    }
    float4 wv = *(const float4*)&ew[base];
    float w[4] = {wv.x, wv.y, wv.z, wv.w};
#pragma unroll
    for (int j = 0; j < 4; j++) {
        if (j < n) {
            int pos = atomicAdd(&g_cursor[clampN(c[j], N)], 1);
            if (pos >= 0 && pos < EMAX)
                g_emeta[pos] = make_int2(clampN(r[j], N), __float_as_int(w[j]));
        }
    }
}

// per-node: weighted degree (self-loop 1 + segment ew sum) -> dinv
__global__ void k_deg(int N) {
    int i = blockIdx.x * blockDim.x + threadIdx.x;
    if (i >= N) return;
    int s = g_rowptr[i], e = g_rowptr[i + 1];
    float d = 1.0f;
    for (int p = s; p < e; p++) d += __int_as_float(g_emeta[p].y);
    g_dinv[i] = rsqrtf(d);
}

// ----------------------------------------------------------------
// HMMA GEMM: C_fp16[M,BN_] = A[M,K] @ B_fp32[K,BN_], fp32 accumulate.
// A is fp32 (layer 0: x) or fp16 (layer 1: g_hh).
template <int BN_, bool AHALF>
__global__ __launch_bounds__(256)
void k_hgemm(const float* __restrict__ Ain, const float* __restrict__ B,
             __half* __restrict__ C, int M, int K) {
    constexpr int BM = 128, BKC = 64;
    constexpr int SA = BKC + 8;
    constexpr int SB = BN_ + 8;
    constexpr int WN = BN_ / 4;
    constexpr int NF = WN / 8;

    __shared__ __half As[BM * SA];
    __shared__ __half Bs[BKC * SB];

    const int tid  = threadIdx.x;
    const int wid  = tid >> 5;
    const int lane = tid & 31;
    const int bm   = blockIdx.x * BM;
    const int warp_m = (wid >> 2) * 64;
    const int warp_n = (wid & 3) * WN;

    float acc[4][NF][4];
#pragma unroll
    for (int i = 0; i < 4; i++)
#pragma unroll
        for (int j = 0; j < NF; j++)
#pragma unroll
            for (int r = 0; r < 4; r++) acc[i][j][r] = 0.0f;

    for (int c0 = 0; c0 < K; c0 += BKC) {
        // stage A chunk: BM x BKC -> fp16 smem
        {
            constexpr int NIT = BM * BKC / 8 / 256;   // 8 elems/thread/iter
#pragma unroll
            for (int p = 0; p < NIT; p++) {
                int idx = p * 256 + tid;
                int row = idx / (BKC / 8);
                int k8  = (idx % (BKC / 8)) * 8;
                int gm  = bm + row;
                __half2 h[4];
                if constexpr (AHALF) {
                    uint4 raw = make_uint4(0, 0, 0, 0);
                    if (gm < M)
                        raw = *(const uint4*)&g_hh[(size_t)gm * K + c0 + k8];
                    h[0] = *(__half2*)&raw.x; h[1] = *(__half2*)&raw.y;
                    h[2] = *(__half2*)&raw.z; h[3] = *(__half2*)&raw.w;
                } else {
                    float4 v0 = make_float4(0.f, 0.f, 0.f, 0.f), v1 = v0;
                    if (gm < M) {
                        const float* p0 = Ain + (size_t)gm * K + c0 + k8;
                        v0 = *(const float4*)(p0);
                        v1 = *(const float4*)(p0 + 4);
                    }
                    h[0] = __floats2half2_rn(v0.x, v0.y);
                    h[1] = __floats2half2_rn(v0.z, v0.w);
                    h[2] = __floats2half2_rn(v1.x, v1.y);
                    h[3] = __floats2half2_rn(v1.z, v1.w);
                }
                __half2* dst = (__half2*)&As[row * SA + k8];
                dst[0] = h[0]; dst[1] = h[1]; dst[2] = h[2]; dst[3] = h[3];
            }
        }
        // stage B chunk: BKC x BN_ fp32 -> fp16 smem
        {
            constexpr int NF4 = BKC * BN_ / 4;
#pragma unroll
            for (int p = 0; p < NF4 / 256; p++) {
                int idx = p * 256 + tid;
                int row = idx / (BN_ / 4);
                int c4  = idx % (BN_ / 4);
                float4 v = *(const float4*)&B[(size_t)(c0 + row) * BN_ + c4 * 4];
                __half2* dst = (__half2*)&Bs[row * SB + c4 * 4];
                dst[0] = __floats2half2_rn(v.x, v.y);
                dst[1] = __floats2half2_rn(v.z, v.w);
            }
        }
        __syncthreads();

#pragma unroll
        for (int ks = 0; ks < BKC / 16; ks++) {
            const int kb = ks * 16;
            uint32_t a[4][4];
#pragma unroll
            for (int mf = 0; mf < 4; mf++) {
                uint32_t addr = (uint32_t)__cvta_generic_to_shared(
                    &As[(warp_m + mf * 16 + (lane & 15)) * SA + kb + (lane >> 4) * 8]);
                asm volatile(
                    "ldmatrix.sync.aligned.m8n8.x4.shared.b16 {%0,%1,%2,%3}, [%4];"
                    : "=r"(a[mf][0]), "=r"(a[mf][1]), "=r"(a[mf][2]), "=r"(a[mf][3])
                    : "r"(addr));
            }
            uint32_t b[NF][2];
#pragma unroll
            for (int nq = 0; nq < NF / 2; nq++) {
                uint32_t addr = (uint32_t)__cvta_generic_to_shared(
                    &Bs[(kb + (lane & 15)) * SB + warp_n + nq * 16 + (lane >> 4) * 8]);
                asm volatile(
                    "ldmatrix.sync.aligned.m8n8.x4.trans.shared.b16 {%0,%1,%2,%3}, [%4];"
                    : "=r"(b[2 * nq][0]), "=r"(b[2 * nq][1]),
                      "=r"(b[2 * nq + 1][0]), "=r"(b[2 * nq + 1][1])
                    : "r"(addr));
            }
#pragma unroll
            for (int mf = 0; mf < 4; mf++)
#pragma unroll
                for (int nf = 0; nf < NF; nf++) {
                    asm volatile(
                        "mma.sync.aligned.m16n8k16.row.col.f32.f16.f16.f32 "
                        "{%0,%1,%2,%3}, {%4,%5,%6,%7}, {%8,%9}, {%0,%1,%2,%3};"
                        : "+f"(acc[mf][nf][0]), "+f"(acc[mf][nf][1]),
                          "+f"(acc[mf][nf][2]), "+f"(acc[mf][nf][3])
                        : "r"(a[mf][0]), "r"(a[mf][1]), "r"(a[mf][2]), "r"(a[mf][3]),
                          "r"(b[nf][0]), "r"(b[nf][1]));
                }
        }
        __syncthreads();
    }

#pragma unroll
    for (int mf = 0; mf < 4; mf++) {
#pragma unroll
        for (int nf = 0; nf < NF; nf++) {
            int col  = warp_n + nf * 8 + 2 * (lane & 3);
            int row0 = bm + warp_m + mf * 16 + (lane >> 2);
            int row1 = row0 + 8;
            if (row0 < M) {
                __half2 h = __floats2half2_rn(acc[mf][nf][0], acc[mf][nf][1]);
                *(__half2*)&C[(size_t)row0 * BN_ + col] = h;
            }
            if (row1 < M) {
                __half2 h = __floats2half2_rn(acc[mf][nf][2], acc[mf][nf][3]);
                *(__half2*)&C[(size_t)row1 * BN_ + col] = h;
            }
        }
    }
}

// ----------------------------------------------------------------
// One warp per destination node: self-loop + CSR gather (fp16 src, fp32 acc)
// + bias + ReLU.  F=128 -> dst fp16 (g_hh); F=64 -> dst fp32 (final out).
template <int F>
__global__ __launch_bounds__(256)
void k_agg(const __half* __restrict__ src, const float* __restrict__ bias,
           float* __restrict__ outbuf, int N) {
    const int gw   = (blockIdx.x * blockDim.x + threadIdx.x) >> 5;
    const int lane = threadIdx.x & 31;
    if (gw >= N) return;

    const int start = g_rowptr[gw];
    const int end   = g_rowptr[gw + 1];
    const float dc  = g_dinv[gw];

    if constexpr (F == 128) {
        float4 acc;
        {
            uint2 raw = ((const uint2*)(src + (size_t)gw * F))[lane];
            float2 a = __half22float2(*(__half2*)&raw.x);
            float2 b = __half22float2(*(__half2*)&raw.y);
            acc = make_float4(dc * a.x, dc * a.y, dc * b.x, dc * b.y);
        }
        int e = start;
        for (; e + 4 <= end; e += 4) {
            int2 m0 = g_emeta[e],     m1 = g_emeta[e + 1];
            int2 m2 = g_emeta[e + 2], m3 = g_emeta[e + 3];
            float w0 = __int_as_float(m0.y) * g_dinv[m0.x];
            float w1 = __int_as_float(m1.y) * g_dinv[m1.x];
            float w2 = __int_as_float(m2.y) * g_dinv[m2.x];
            float w3 = __int_as_float(m3.y) * g_dinv[m3.x];
            uint2 r0 = ((const uint2*)(src + (size_t)m0.x * F))[lane];
            uint2 r1 = ((const uint2*)(src + (size_t)m1.x * F))[lane];
            uint2 r2 = ((const uint2*)(src + (size_t)m2.x * F))[lane];
            uint2 r3 = ((const uint2*)(src + (size_t)m3.x * F))[lane];
            float2 a0 = __half22float2(*(__half2*)&r0.x), b0 = __half22float2(*(__half2*)&r0.y);
            float2 a1 = __half22float2(*(__half2*)&r1.x), b1 = __half22float2(*(__half2*)&r1.y);
            float2 a2 = __half22float2(*(__half2*)&r2.x), b2 = __half22float2(*(__half2*)&r2.y);
            float2 a3 = __half22float2(*(__half2*)&r3.x), b3 = __half22float2(*(__half2*)&r3.y);
            acc.x += w0 * a0.x + w1 * a1.x + w2 * a2.x + w3 * a3.x;
            acc.y += w0 * a0.y + w1 * a1.y + w2 * a2.y + w3 * a3.y;
            acc.z += w0 * b0.x + w1 * b1.x + w2 * b2.x + w3 * b3.x;
            acc.w += w0 * b0.y + w1 * b1.y + w2 * b2.y + w3 * b3.y;
        }
        for (; e < end; e++) {
            int2 m = g_emeta[e];
            float w = __int_as_float(m.y) * g_dinv[m.x];
            uint2 r = ((const uint2*)(src + (size_t)m.x * F))[lane];
            float2 a = __half22float2(*(__half2*)&r.x);
            float2 b = __half22float2(*(__half2*)&r.y);
            acc.x += w * a.x; acc.y += w * a.y;
            acc.z += w * b.x; acc.w += w * b.y;
        }
        float4 bv = ((const float4*)bias)[lane];
        acc.x = fmaxf(dc * acc.x + bv.x, 0.f);
        acc.y = fmaxf(dc * acc.y + bv.y, 0.f);
        acc.z = fmaxf(dc * acc.z + bv.z, 0.f);
        acc.w = fmaxf(dc * acc.w + bv.w, 0.f);
        uint2 hout;
        *(__half2*)&hout.x = __floats2half2_rn(acc.x, acc.y);
        *(__half2*)&hout.y = __floats2half2_rn(acc.z, acc.w);
        ((uint2*)(g_hh + (size_t)gw * F))[lane] = hout;
    } else {
        float2 acc;
        {
            unsigned raw = ((const unsigned*)(src + (size_t)gw * F))[lane];
            float2 a = __half22float2(*(__half2*)&raw);
            acc = make_float2(dc * a.x, dc * a.y);
        }
        int e = start;
        for (; e + 4 <= end; e += 4) {
            int2 m0 = g_emeta[e],     m1 = g_emeta[e + 1];
            int2 m2 = g_emeta[e + 2], m3 = g_emeta[e + 3];
            float w0 = __int_as_float(m0.y) * g_dinv[m0.x];
            float w1 = __int_as_float(m1.y) * g_dinv[m1.x];
            float w2 = __int_as_float(m2.y) * g_dinv[m2.x];
            float w3 = __int_as_float(m3.y) * g_dinv[m3.x];
            unsigned r0 = ((const unsigned*)(src + (size_t)m0.x * F))[lane];
            unsigned r1 = ((const unsigned*)(src + (size_t)m1.x * F))[lane];
            unsigned r2 = ((const unsigned*)(src + (size_t)m2.x * F))[lane];
            unsigned r3 = ((const unsigned*)(src + (size_t)m3.x * F))[lane];
            float2 a0 = __half22float2(*(__half2*)&r0);
            float2 a1 = __half22float2(*(__half2*)&r1);
            float2 a2 = __half22float2(*(__half2*)&r2);
            float2 a3 = __half22float2(*(__half2*)&r3);
            acc.x += w0 * a0.x + w1 * a1.x + w2 * a2.x + w3 * a3.x;
            acc.y += w0 * a0.y + w1 * a1.y + w2 * a2.y + w3 * a3.y;
        }
        for (; e < end; e++) {
            int2 m = g_emeta[e];
            float w = __int_as_float(m.y) * g_dinv[m.x];
            unsigned r = ((const unsigned*)(src + (size_t)m.x * F))[lane];
            float2 a = __half22float2(*(__half2*)&r);
            acc.x += w * a.x; acc.y += w * a.y;
        }
        float2 bv = ((const float2*)bias)[lane];
        acc.x = fmaxf(dc * acc.x + bv.x, 0.f);
        acc.y = fmaxf(dc * acc.y + bv.y, 0.f);
        ((float2*)(outbuf + (size_t)gw * F))[lane] = acc;
    }
}

// ----------------------------------------------------------------
extern "C" void kernel_launch(void* const* d_in, const int* in_sizes, int n_in,
                              void* d_out, int out_size) {
    const float* x    = (const float*)d_in[0];
    const int*   ei32 = (const int*)d_in[1];     // raw words; dtype probed on device
    const float* ew   = (const float*)d_in[2];
    const float* W0   = (const float*)d_in[3];
    const float* b0   = (const float*)d_in[4];
    const float* W1   = (const float*)d_in[5];
    const float* b1   = (const float*)d_in[6];
    float* out = (float*)d_out;

    const int Fh  = in_sizes[4];            // 128
    const int Fo  = in_sizes[6];            // 64
    const int Fin = in_sizes[3] / Fh;       // 128
    const int N   = in_sizes[0] / Fin;      // 50000
    const int E   = in_sizes[2];            // 800000

    // side stream + events, created once on the first (uncaptured) call
    static cudaStream_t s2 = nullptr;
    static cudaEvent_t evFork = nullptr, evJoin = nullptr;
    if (s2 == nullptr) {
        cudaStreamCreateWithFlags(&s2, cudaStreamNonBlocking);
        cudaEventCreateWithFlags(&evFork, cudaEventDisableTiming);
        cudaEventCreateWithFlags(&evJoin, cudaEventDisableTiming);
    }

    __half* xwh = nullptr; cudaGetSymbolAddress((void**)&xwh, g_xwh);
    __half* hwh = nullptr; cudaGetSymbolAddress((void**)&hwh, g_hwh);

    const int TB = 256;
    const int nScanBlocks = (N + 1023) / 1024;
    const int diGrid = ((N > 65536 ? N : 65536) + TB - 1) / TB;

    // fork: GEMM-1 (depends only on inputs) runs on s2, overlapping CSR prep
    cudaEventRecord(evFork, 0);
    cudaStreamWaitEvent(s2, evFork, 0);
    k_hgemm<128, false><<<(N + 127) / 128, 256, 0, s2>>>(x, W0, xwh, N, Fin);
    cudaEventRecord(evJoin, s2);

    // CSR prep chain on the main stream
    k_detect_init<<<diGrid, TB>>>(ei32, E, N);
    k_count<<<(E / 4 + TB - 1) / TB, TB>>>(ei32, E, N);
    k_scan_onepass<<<nScanBlocks, 1024>>>(N, E);
    k_place<<<(E / 4 + TB - 1) / TB, TB>>>(ei32, ew, E, N);
    k_deg<<<(N + TB - 1) / TB, TB>>>(N);

    // join: agg-1 needs both CSR prep and GEMM-1
    cudaStreamWaitEvent(0, evJoin, 0);
    k_agg<128><<<(N * 32 + TB - 1) / TB, TB>>>(xwh, b0, nullptr, N);

    // layer 2
    k_hgemm<64, true><<<(N + 127) / 128, 256>>>(nullptr, W1, hwh, N, Fh);
    k_agg<64><<<(N * 32 + TB - 1) / TB, TB>>>(hwh, b1, out, N);
}